// round 1
// baseline (speedup 1.0000x reference)
#include <cuda_runtime.h>
#include <cuda_bf16.h>

// DotProductAttention: inp (B=4, C=80, H=512, W=512) fp32, channel-major.
//   q = inp[:, 0:8], k = inp[:, 8:72] viewed (8,8), v = inp[:, 72:80]
//   qk[v] = sum_k q[k]*k[k,v] / sqrt(8);  attn = softmax over v;  out = attn*v
// Pure HBM-bound: 320B in + 32B out per pixel. One thread = 4 pixels (float4).

#define NKq 8
#define NVq 8
#define HW_   (512 * 512)
#define HW4_  (HW_ / 4)          // 65536 float4 groups per plane
#define NCH   (NKq + NKq * NVq + NVq)   // 80

__global__ void __launch_bounds__(256, 8)
dpa_kernel(const float4* __restrict__ inp, float4* __restrict__ out)
{
    const int idx = blockIdx.x * blockDim.x + threadIdx.x;   // 0 .. B*HW4-1
    const int b = idx >> 16;            // idx / HW4_ (HW4_ = 65536)
    const int r = idx & (HW4_ - 1);

    const float4* __restrict__ base = inp + (size_t)b * NCH * HW4_ + r;

    // ---- load q (8 channels, coalesced 16B loads) ----
    float q[NKq][4];
#pragma unroll
    for (int i = 0; i < NKq; i++) {
        float4 t = base[i * HW4_];
        q[i][0] = t.x; q[i][1] = t.y; q[i][2] = t.z; q[i][3] = t.w;
    }

    // ---- stream k (64 channels), accumulate qk[v] ----
    float qk[NVq][4];
#pragma unroll
    for (int v = 0; v < NVq; v++)
        qk[v][0] = qk[v][1] = qk[v][2] = qk[v][3] = 0.0f;

#pragma unroll
    for (int kk = 0; kk < NKq; kk++) {
#pragma unroll
        for (int v = 0; v < NVq; v++) {
            float4 t = base[(NKq + kk * NVq + v) * HW4_];
            qk[v][0] = fmaf(q[kk][0], t.x, qk[v][0]);
            qk[v][1] = fmaf(q[kk][1], t.y, qk[v][1]);
            qk[v][2] = fmaf(q[kk][2], t.z, qk[v][2]);
            qk[v][3] = fmaf(q[kk][3], t.w, qk[v][3]);
        }
    }

    // ---- scale + softmax over the v axis (8 values), per pixel component ----
    const float scale = 0.35355339059327373f;   // 1/sqrt(8)
    float inv_sum[4];
#pragma unroll
    for (int c = 0; c < 4; c++) {
        float m = qk[0][c];
#pragma unroll
        for (int v = 1; v < NVq; v++) m = fmaxf(m, qk[v][c]);
        float s = 0.0f;
#pragma unroll
        for (int v = 0; v < NVq; v++) {
            float e = __expf((qk[v][c] - m) * scale);
            qk[v][c] = e;                 // reuse qk regs for exp values
            s += e;
        }
        inv_sum[c] = __frcp_rn(s);
    }

    // ---- stream v (8 channels), multiply, write out ----
    float4* __restrict__ obase = out + (size_t)b * NVq * HW4_ + r;
#pragma unroll
    for (int v = 0; v < NVq; v++) {
        float4 t = base[(NKq + NKq * NVq + v) * HW4_];
        float4 o;
        o.x = qk[v][0] * inv_sum[0] * t.x;
        o.y = qk[v][1] * inv_sum[1] * t.y;
        o.z = qk[v][2] * inv_sum[2] * t.z;
        o.w = qk[v][3] * inv_sum[3] * t.w;
        obase[v * HW4_] = o;
    }
}

extern "C" void kernel_launch(void* const* d_in, const int* in_sizes, int n_in,
                              void* d_out, int out_size)
{
    const float4* inp = (const float4*)d_in[0];
    float4* out = (float4*)d_out;
    const int total = 4 * HW4_;          // B * HW/4 threads
    dpa_kernel<<<total / 256, 256>>>(inp, out);
}

// round 2
// speedup vs baseline: 1.1617x; 1.1617x over previous
#include <cuda_runtime.h>
#include <cuda_bf16.h>

// DotProductAttention: inp (B=4, C=80, H=512, W=512) fp32, channel-major.
// Pure HBM stream: 320B in + 32B out per pixel. 2 pixels/thread (float2)
// keeps live state at ~48 regs (no spill), streaming cache hints everywhere.

#define NKq 8
#define NVq 8
#define HW_   (512 * 512)
#define HW2_  (HW_ / 2)          // 131072 float2 groups per plane
#define NCH   (NKq + NKq * NVq + NVq)   // 80

__global__ void __launch_bounds__(256, 3)
dpa_kernel(const float2* __restrict__ inp, float2* __restrict__ out)
{
    const int idx = blockIdx.x * blockDim.x + threadIdx.x;   // 0 .. B*HW2-1
    const int b = idx >> 17;            // idx / HW2_ (HW2_ = 131072)
    const int r = idx & (HW2_ - 1);

    const float2* __restrict__ base = inp + (size_t)b * NCH * HW2_ + r;

    // ---- load q (8 channels, coalesced 8B loads, evict-first) ----
    float q[NKq][2];
#pragma unroll
    for (int i = 0; i < NKq; i++) {
        float2 t = __ldcs(&base[i * HW2_]);
        q[i][0] = t.x; q[i][1] = t.y;
    }

    // ---- stream k (64 channels), accumulate qk[v] ----
    float qk[NVq][2];
#pragma unroll
    for (int v = 0; v < NVq; v++)
        qk[v][0] = qk[v][1] = 0.0f;

#pragma unroll
    for (int kk = 0; kk < NKq; kk++) {
#pragma unroll
        for (int v = 0; v < NVq; v++) {
            float2 t = __ldcs(&base[(NKq + kk * NVq + v) * HW2_]);
            qk[v][0] = fmaf(q[kk][0], t.x, qk[v][0]);
            qk[v][1] = fmaf(q[kk][1], t.y, qk[v][1]);
        }
    }

    // ---- scale + softmax over v axis (8 values), per pixel component ----
    const float scale = 0.35355339059327373f;   // 1/sqrt(8)
    float inv_sum[2];
#pragma unroll
    for (int c = 0; c < 2; c++) {
        float m = qk[0][c];
#pragma unroll
        for (int v = 1; v < NVq; v++) m = fmaxf(m, qk[v][c]);
        float s = 0.0f;
#pragma unroll
        for (int v = 0; v < NVq; v++) {
            float e = __expf((qk[v][c] - m) * scale);
            qk[v][c] = e;                 // reuse qk regs for exp values
            s += e;
        }
        inv_sum[c] = __frcp_rn(s);
    }

    // ---- stream v (8 channels), multiply, write out (evict-first) ----
    float2* __restrict__ obase = out + (size_t)b * NVq * HW2_ + r;
#pragma unroll
    for (int v = 0; v < NVq; v++) {
        float2 t = __ldcs(&base[(NKq + NKq * NVq + v) * HW2_]);
        float2 o;
        o.x = qk[v][0] * inv_sum[0] * t.x;
        o.y = qk[v][1] * inv_sum[1] * t.y;
        __stcs(&obase[v * HW2_], o);
    }
}

extern "C" void kernel_launch(void* const* d_in, const int* in_sizes, int n_in,
                              void* d_out, int out_size)
{
    const float2* inp = (const float2*)d_in[0];
    float2* out = (float2*)d_out;
    const int total = 4 * HW2_;          // B * HW/2 threads
    dpa_kernel<<<total / 256, 256>>>(inp, out);
}

// round 3
// speedup vs baseline: 1.3593x; 1.1700x over previous
#include <cuda_runtime.h>
#include <cuda_bf16.h>

// DotProductAttention: inp (B=4, C=80, H=512, W=512) fp32, channel-major.
// Pure HBM stream: 320B in + 32B out per pixel. 4 pixels/thread (float4,
// 16B coalesced loads) with a 128-reg budget: state (64 floats) fits,
// ~50 regs left for load batching -> deep MLP to hide ~600cyc DRAM latency.

#define NKq 8
#define NVq 8
#define HW_   (512 * 512)
#define HW4_  (HW_ / 4)          // 65536 float4 groups per plane
#define NCH   (NKq + NKq * NVq + NVq)   // 80

__global__ void __launch_bounds__(256, 2)
dpa_kernel(const float4* __restrict__ inp, float4* __restrict__ out)
{
    const int idx = blockIdx.x * blockDim.x + threadIdx.x;   // 0 .. B*HW4-1
    const int b = idx >> 16;            // idx / HW4_ (HW4_ = 65536)
    const int r = idx & (HW4_ - 1);

    const float4* __restrict__ base = inp + (size_t)b * NCH * HW4_ + r;

    // ---- load q (8 channels, 16B coalesced, evict-first) ----
    float4 q[NKq];
#pragma unroll
    for (int i = 0; i < NKq; i++)
        q[i] = __ldcs(&base[i * HW4_]);

    // ---- stream k (64 channels), accumulate qk[v]; batch 8 loads per kk ----
    float4 qk[NVq];
#pragma unroll
    for (int v = 0; v < NVq; v++)
        qk[v] = make_float4(0.f, 0.f, 0.f, 0.f);

#pragma unroll
    for (int kk = 0; kk < NKq; kk++) {
        float4 t[NVq];
#pragma unroll
        for (int v = 0; v < NVq; v++)
            t[v] = __ldcs(&base[(NKq + kk * NVq + v) * HW4_]);
#pragma unroll
        for (int v = 0; v < NVq; v++) {
            qk[v].x = fmaf(q[kk].x, t[v].x, qk[v].x);
            qk[v].y = fmaf(q[kk].y, t[v].y, qk[v].y);
            qk[v].z = fmaf(q[kk].z, t[v].z, qk[v].z);
            qk[v].w = fmaf(q[kk].w, t[v].w, qk[v].w);
        }
    }

    // ---- scale + softmax over v axis (8 values), per pixel component ----
    const float scale = 0.35355339059327373f;   // 1/sqrt(8)
    float4 m = qk[0];
#pragma unroll
    for (int v = 1; v < NVq; v++) {
        m.x = fmaxf(m.x, qk[v].x); m.y = fmaxf(m.y, qk[v].y);
        m.z = fmaxf(m.z, qk[v].z); m.w = fmaxf(m.w, qk[v].w);
    }
    float4 s = make_float4(0.f, 0.f, 0.f, 0.f);
#pragma unroll
    for (int v = 0; v < NVq; v++) {
        qk[v].x = __expf((qk[v].x - m.x) * scale);
        qk[v].y = __expf((qk[v].y - m.y) * scale);
        qk[v].z = __expf((qk[v].z - m.z) * scale);
        qk[v].w = __expf((qk[v].w - m.w) * scale);
        s.x += qk[v].x; s.y += qk[v].y; s.z += qk[v].z; s.w += qk[v].w;
    }
    float4 inv;
    inv.x = __frcp_rn(s.x); inv.y = __frcp_rn(s.y);
    inv.z = __frcp_rn(s.z); inv.w = __frcp_rn(s.w);

    // ---- stream v (8 channels), multiply, write out (evict-first) ----
    float4* __restrict__ obase = out + (size_t)b * NVq * HW4_ + r;
#pragma unroll
    for (int v = 0; v < NVq; v++) {
        float4 t = __ldcs(&base[(NKq + NKq * NVq + v) * HW4_]);
        float4 o;
        o.x = qk[v].x * inv.x * t.x;
        o.y = qk[v].y * inv.y * t.y;
        o.z = qk[v].z * inv.z * t.z;
        o.w = qk[v].w * inv.w * t.w;
        __stcs(&obase[v * HW4_], o);
    }
}

extern "C" void kernel_launch(void* const* d_in, const int* in_sizes, int n_in,
                              void* d_out, int out_size)
{
    const float4* inp = (const float4*)d_in[0];
    float4* out = (float4*)d_out;
    const int total = 4 * HW4_;          // B * HW/4 threads
    dpa_kernel<<<total / 256, 256>>>(inp, out);
}